// round 12
// baseline (speedup 1.0000x reference)
#include <cuda_runtime.h>
#include <cuda_fp16.h>
#include <cstdint>
#include <cstddef>

// ---------------- problem constants ----------------
#define NCLS      50257
#define NCLS_PAD  50432            // 394 * 128
#define DM        2048
#define BATCH     2048
#define HID       128
#define NB        8
#define RK        4
#define KEXT      32               // NB*RK
#define KTOT      2112             // 2048 + 64-pad -> 33*64
#define KCH       64               // halves per K chunk (128 bytes)
#define NCHUNK    33
#define LN_EPS    1e-5f

#define M_TILE    128              // classes per CTA
#define N_TILE    256              // batch per CTA
#define CT_TILES  394
#define BT_TILES  8
#define GTHREADS  512              // 16 warps: 2(m) x 8(n), warp tile 64x32

// smem: 4 stages x (A 16KB | B 32KB); epilogue reuses it as fp32 tile
#define STAGE_BYTES 49152
#define SM_B_OFF    16384
#define EPLD        132
#define DYN_SMEM    (4 * STAGE_BYTES)        // 196608

// ---------------- device scratch ----------------
__device__ __align__(1024) __half g_W2[(size_t)NCLS_PAD * KTOT];  // ~213 MB
__device__ __align__(1024) __half g_A2[(size_t)BATCH * KTOT];     // ~8.7 MB
__device__ float g_coeffs[BATCH * NB];
__device__ float g_y[BATCH * NB * RK];

// ---------------- PTX helpers (base PTX only) ----------------
__device__ __forceinline__ uint32_t smem_u32(const void* p) {
    return (uint32_t)__cvta_generic_to_shared(p);
}
__device__ __forceinline__ void cp16(uint32_t dst, const void* src) {
    asm volatile("cp.async.cg.shared.global [%0], [%1], 16;" :: "r"(dst), "l"(src) : "memory");
}
__device__ __forceinline__ void ldsm4(uint32_t* r, uint32_t a) {
    asm volatile("ldmatrix.sync.aligned.m8n8.x4.shared.b16 {%0,%1,%2,%3}, [%4];"
                 : "=r"(r[0]), "=r"(r[1]), "=r"(r[2]), "=r"(r[3]) : "r"(a));
}
__device__ __forceinline__ void mma16816(float* c, const uint32_t* a,
                                         uint32_t b0, uint32_t b1) {
    asm volatile(
        "mma.sync.aligned.m16n8k16.row.col.f32.f16.f16.f32 "
        "{%0,%1,%2,%3}, {%4,%5,%6,%7}, {%8,%9}, {%0,%1,%2,%3};"
        : "+f"(c[0]), "+f"(c[1]), "+f"(c[2]), "+f"(c[3])
        : "r"(a[0]), "r"(a[1]), "r"(a[2]), "r"(a[3]), "r"(b0), "r"(b1));
}

// ============================================================================
// prep kernels (unchanged from R10 — they earned their keep)
// ============================================================================

__global__ void k_conv_x(const float* __restrict__ x) {
    int gid = blockIdx.x * blockDim.x + threadIdx.x;
    const float4* xv = (const float4*)x;
    float4 a = xv[gid * 2];
    float4 b = xv[gid * 2 + 1];
    __half2 p[4];
    p[0] = __floats2half2_rn(a.x, a.y);
    p[1] = __floats2half2_rn(a.z, a.w);
    p[2] = __floats2half2_rn(b.x, b.y);
    p[3] = __floats2half2_rn(b.z, b.w);
    int brow = gid >> 8;
    int col8 = gid & 255;
    *(uint4*)(g_A2 + (size_t)brow * KTOT + col8 * 8) = *(uint4*)p;
}

__global__ void k_prep_w2(const float* __restrict__ base_w,
                          const float* __restrict__ basis_B) {
    int c = blockIdx.x;
    int t = threadIdx.x;
    __half* dst = g_W2 + (size_t)c * KTOT;
    if (c >= NCLS) {
        uint4 z = {0, 0, 0, 0};
        *(uint4*)(dst + t * 8) = z;
        if (t < 8) *(uint4*)(dst + DM + t * 8) = z;
        return;
    }
    {
        const float4* p = (const float4*)(base_w + (size_t)c * DM + t * 8);
        float4 a = p[0], b = p[1];
        __half h[8];
        h[0] = __float2half_rn(a.x); h[1] = __float2half_rn(a.y);
        h[2] = __float2half_rn(a.z); h[3] = __float2half_rn(a.w);
        h[4] = __float2half_rn(b.x); h[5] = __float2half_rn(b.y);
        h[6] = __float2half_rn(b.z); h[7] = __float2half_rn(b.w);
        *(uint4*)(dst + t * 8) = *(uint4*)h;
    }
    if (t < 8) {
        __half h[8];
        #pragma unroll
        for (int j = 0; j < 8; j++) {
            int idx = t * 8 + j;
            if (idx < KEXT) {
                int n = idx >> 2, r = idx & 3;
                h[j] = __float2half_rn(basis_B[((size_t)n * NCLS + c) * RK + r]);
            } else {
                h[j] = __ushort_as_half(0);
            }
        }
        *(uint4*)(dst + DM + t * 8) = *(uint4*)h;
    }
}

__global__ void __launch_bounds__(256)
k_ctx(const float* __restrict__ context,
      const float* __restrict__ ctx_w,
      const float* __restrict__ ctx_b,
      const float* __restrict__ ln_g,
      const float* __restrict__ ln_b,
      const float* __restrict__ coeff_w,
      const float* __restrict__ coeff_b) {
    __shared__ float sX[8][DM];
    __shared__ float sH[8][HID + 4];
    int tid = threadIdx.x;
    int b0 = blockIdx.x * 8;

    #pragma unroll
    for (int i = 0; i < 16; i++) {
        int e = tid + i * 256;
        int r = e >> 9, d4 = e & 511;
        *(float4*)&sX[r][d4 * 4] =
            *(const float4*)(context + (size_t)(b0 + r) * DM + d4 * 4);
    }
    __syncthreads();

    const int jq = tid >> 3;
    const int dg = tid & 7;
    float acc[8][4];
    #pragma unroll
    for (int r = 0; r < 8; r++)
        #pragma unroll
        for (int jj = 0; jj < 4; jj++) acc[r][jj] = 0.f;

    #pragma unroll 4
    for (int kk = 0; kk < DM; kk += 32) {
        float4 w4[4];
        #pragma unroll
        for (int jj = 0; jj < 4; jj++)
            w4[jj] = *(const float4*)(ctx_w + (size_t)(jq * 4 + jj) * DM + kk + dg * 4);
        #pragma unroll
        for (int r = 0; r < 8; r++) {
            float4 x4 = *(float4*)&sX[r][kk + dg * 4];
            #pragma unroll
            for (int jj = 0; jj < 4; jj++)
                acc[r][jj] += x4.x * w4[jj].x + x4.y * w4[jj].y +
                              x4.z * w4[jj].z + x4.w * w4[jj].w;
        }
    }
    #pragma unroll
    for (int off = 1; off < 8; off <<= 1)
        #pragma unroll
        for (int r = 0; r < 8; r++)
            #pragma unroll
            for (int jj = 0; jj < 4; jj++)
                acc[r][jj] += __shfl_xor_sync(0xffffffffu, acc[r][jj], off);
    if (dg == 0) {
        #pragma unroll
        for (int r = 0; r < 8; r++)
            #pragma unroll
            for (int jj = 0; jj < 4; jj++)
                sH[r][jq * 4 + jj] = acc[r][jj] + ctx_b[jq * 4 + jj];
    }
    __syncthreads();

    int wid = tid >> 5, lane = tid & 31;
    float v[4];
    #pragma unroll
    for (int j = 0; j < 4; j++) v[j] = sH[wid][lane * 4 + j];
    float s1 = v[0] + v[1] + v[2] + v[3];
    float s2 = v[0]*v[0] + v[1]*v[1] + v[2]*v[2] + v[3]*v[3];
    #pragma unroll
    for (int m = 16; m; m >>= 1) {
        s1 += __shfl_xor_sync(0xffffffffu, s1, m);
        s2 += __shfl_xor_sync(0xffffffffu, s2, m);
    }
    float mu = s1 * (1.0f / HID);
    float var = s2 * (1.0f / HID) - mu * mu;
    float inv = rsqrtf(var + LN_EPS);
    #pragma unroll
    for (int j = 0; j < 4; j++) {
        float hn = (v[j] - mu) * inv * ln_g[lane * 4 + j] + ln_b[lane * 4 + j];
        v[j] = 0.5f * hn * (1.0f + erff(hn * 0.70710678118654752f));
    }
    #pragma unroll
    for (int n = 0; n < NB; n++) {
        float d = 0.f;
        #pragma unroll
        for (int j = 0; j < 4; j++) d += v[j] * coeff_w[(size_t)n * HID + lane * 4 + j];
        #pragma unroll
        for (int m = 16; m; m >>= 1) d += __shfl_xor_sync(0xffffffffu, d, m);
        if (lane == 0) g_coeffs[(size_t)(b0 + wid) * NB + n] = d + coeff_b[n];
    }
}

__global__ void __launch_bounds__(256)
k_y_gemm(const float* __restrict__ x, const float* __restrict__ basis_A) {
    __shared__ float sX[4][DM];
    int tid = threadIdx.x;
    int b0 = blockIdx.x * 4;
    #pragma unroll
    for (int i = 0; i < 8; i++) {
        int e = tid + i * 256;
        int r = e >> 9, d4 = e & 511;
        *(float4*)&sX[r][d4 * 4] =
            *(const float4*)(x + (size_t)(b0 + r) * DM + d4 * 4);
    }
    __syncthreads();

    const int nr = tid >> 3;
    const int dg = tid & 7;
    float acc[4] = {};
    #pragma unroll 4
    for (int kk = 0; kk < DM; kk += 32) {
        float4 w4 = *(const float4*)(basis_A + (size_t)nr * DM + kk + dg * 4);
        #pragma unroll
        for (int r = 0; r < 4; r++) {
            float4 x4 = *(float4*)&sX[r][kk + dg * 4];
            acc[r] += x4.x * w4.x + x4.y * w4.y + x4.z * w4.z + x4.w * w4.w;
        }
    }
    #pragma unroll
    for (int off = 1; off < 8; off <<= 1)
        #pragma unroll
        for (int r = 0; r < 4; r++)
            acc[r] += __shfl_xor_sync(0xffffffffu, acc[r], off);
    if (dg == 0) {
        #pragma unroll
        for (int r = 0; r < 4; r++)
            g_y[(size_t)(b0 + r) * 32 + nr] = acc[r];
    }
}

__global__ void k_u_fill() {
    int row = blockIdx.x * blockDim.x + threadIdx.x;
    if (row >= BATCH) return;
    float c[NB], z[RK] = {};
    #pragma unroll
    for (int n = 0; n < NB; n++) c[n] = g_coeffs[(size_t)row * NB + n];
    #pragma unroll
    for (int n = 0; n < NB; n++)
        #pragma unroll
        for (int r = 0; r < RK; r++) z[r] += c[n] * g_y[(size_t)row * 32 + n * RK + r];
    __half u[KEXT];
    #pragma unroll
    for (int n = 0; n < NB; n++)
        #pragma unroll
        for (int r = 0; r < RK; r++) u[n * RK + r] = __float2half_rn(c[n] * z[r]);
    __half* dst = g_A2 + (size_t)row * KTOT + DM;
    #pragma unroll
    for (int j = 0; j < KEXT; j++) dst[j] = u[j];
    #pragma unroll
    for (int j = 0; j < 32; j++) dst[KEXT + j] = __ushort_as_half(0);
}

// ============================================================================
// main GEMM (HMMA): D[class][batch] = W2 @ A2^T + base_b
// CTA: 128 cls x 256 batch, 512 threads = 16 warps as 2(m) x 8(n),
// warp tile 64x32 -> acc 64 regs/thread, 4 warps per SMSP
// ============================================================================

__device__ __forceinline__ void load_chunk(int ct, int bt, int chunk,
                                           uint32_t sb, int tid) {
    #pragma unroll
    for (int i = 0; i < 6; i++) {
        int e = tid + i * GTHREADS;            // 0..3071
        const __half* src;
        uint32_t dst;
        if (e < 1024) {                        // A: 128 class rows x 8 segs
            int r = e >> 3, seg = e & 7;
            src = g_W2 + (size_t)(ct * M_TILE + r) * KTOT + chunk * KCH + seg * 8;
            dst = sb + r * 128 + ((seg ^ (r & 7)) << 4);
        } else {                               // B: 256 batch rows x 8 segs
            int e2 = e - 1024;
            int r = e2 >> 3, seg = e2 & 7;
            src = g_A2 + (size_t)(bt * N_TILE + r) * KTOT + chunk * KCH + seg * 8;
            dst = sb + SM_B_OFF + r * 128 + ((seg ^ (r & 7)) << 4);
        }
        cp16(dst, src);
    }
}

__global__ void __launch_bounds__(GTHREADS, 1)
k_gemm(float* __restrict__ out, const float* __restrict__ base_b) {
    extern __shared__ char smem[];
    const uint32_t smb = smem_u32(smem);
    const int tid = threadIdx.x;
    const int wid = tid >> 5, lane = tid & 31;
    const int bt = blockIdx.x & 7;
    const int ct = blockIdx.x >> 3;
    const int wm = (wid & 1) * 64;             // warp m (class) offset
    const int wn = (wid >> 1) * 32;            // warp n (batch) offset

    const int j = lane >> 3, rl = lane & 7;
    const int arow = wm + ((j & 1) << 3) + rl;
    const int brow = wn + ((j & 1) << 3) + rl;
    const int usel = j >> 1;

    float acc[4][4][4];                        // [mt][n8 tile][4]
    #pragma unroll
    for (int a = 0; a < 4; a++)
        #pragma unroll
        for (int b = 0; b < 4; b++)
            #pragma unroll
            for (int cc = 0; cc < 4; cc++) acc[a][b][cc] = 0.f;

    #pragma unroll
    for (int c = 0; c < 3; c++) {
        load_chunk(ct, bt, c, smb + c * STAGE_BYTES, tid);
        asm volatile("cp.async.commit_group;" ::: "memory");
    }

    #pragma unroll 1
    for (int c = 0; c < NCHUNK; c++) {
        const uint32_t sb = smb + (c & 3) * STAGE_BYTES;
        asm volatile("cp.async.wait_group 2;" ::: "memory");
        __syncthreads();

        int n = c + 3;
        if (n < NCHUNK) load_chunk(ct, bt, n, smb + (n & 3) * STAGE_BYTES, tid);
        asm volatile("cp.async.commit_group;" ::: "memory");

        #pragma unroll
        for (int k16 = 0; k16 < 4; k16++) {
            uint32_t af[4][4], bf[2][4];
            #pragma unroll
            for (int mt = 0; mt < 4; mt++) {
                int row = arow + mt * 16;
                ldsm4(af[mt], sb + row * 128 + (((k16 * 2 + usel) ^ (row & 7)) << 4));
            }
            #pragma unroll
            for (int nt2 = 0; nt2 < 2; nt2++) {
                int row = brow + nt2 * 16;
                ldsm4(bf[nt2], sb + SM_B_OFF + row * 128 +
                               (((k16 * 2 + usel) ^ (row & 7)) << 4));
            }
            #pragma unroll
            for (int mt = 0; mt < 4; mt++)
                #pragma unroll
                for (int nt2 = 0; nt2 < 2; nt2++) {
                    mma16816(acc[mt][2 * nt2 + 0], af[mt], bf[nt2][0], bf[nt2][2]);
                    mma16816(acc[mt][2 * nt2 + 1], af[mt], bf[nt2][1], bf[nt2][3]);
                }
        }
    }

    // epilogue: stage through smem, store coalesced
    asm volatile("cp.async.wait_group 0;" ::: "memory");
    __syncthreads();

    float* ep = (float*)smem;                  // 256 rows x EPLD floats
    const int mr = lane >> 2;
    const int nc = (lane & 3) * 2;

    #pragma unroll
    for (int mt = 0; mt < 4; mt++)
        #pragma unroll
        for (int rep = 0; rep < 2; rep++) {
            int cl = wm + mt * 16 + rep * 8 + mr;
            #pragma unroll
            for (int nt = 0; nt < 4; nt++) {
                int bl = wn + nt * 8 + nc;
                ep[bl * EPLD + cl]       = acc[mt][nt][rep * 2 + 0];
                ep[(bl + 1) * EPLD + cl] = acc[mt][nt][rep * 2 + 1];
            }
        }
    __syncthreads();

    const int cls_base = ct * M_TILE;
    float bias[4];
    bool okc[4];
    #pragma unroll
    for (int jj = 0; jj < 4; jj++) {
        int cls = cls_base + jj * 32 + lane;
        okc[jj] = (cls < NCLS);
        bias[jj] = okc[jj] ? base_b[cls] : 0.f;
    }
    #pragma unroll 1
    for (int r = wid; r < N_TILE; r += 16) {
        size_t obase = (size_t)(bt * N_TILE + r) * NCLS + cls_base;
        const float* erow = ep + r * EPLD;
        #pragma unroll
        for (int jj = 0; jj < 4; jj++)
            if (okc[jj])
                out[obase + jj * 32 + lane] = erow[jj * 32 + lane] + bias[jj];
    }
}

// ============================================================================
// launch
// ============================================================================
extern "C" void kernel_launch(void* const* d_in, const int* in_sizes, int n_in,
                              void* d_out, int out_size) {
    const float* x        = (const float*)d_in[0];
    const float* context  = (const float*)d_in[1];
    const float* base_w   = (const float*)d_in[2];
    const float* base_b   = (const float*)d_in[3];
    const float* ctx_w    = (const float*)d_in[4];
    const float* ctx_b    = (const float*)d_in[5];
    const float* ln_g     = (const float*)d_in[6];
    const float* ln_b     = (const float*)d_in[7];
    const float* coeff_w  = (const float*)d_in[8];
    const float* coeff_b  = (const float*)d_in[9];
    const float* basis_A  = (const float*)d_in[10];
    const float* basis_B  = (const float*)d_in[11];
    float* out = (float*)d_out;

    cudaFuncSetAttribute(k_gemm, cudaFuncAttributeMaxDynamicSharedMemorySize, DYN_SMEM);

    k_prep_w2<<<NCLS_PAD, 256>>>(base_w, basis_B);                   // 0
    k_conv_x<<<BATCH * DM / 8 / 256, 256>>>(x);                      // 1
    k_ctx<<<BATCH / 8, 256>>>(context, ctx_w, ctx_b, ln_g, ln_b, coeff_w, coeff_b); // 2
    k_y_gemm<<<BATCH / 4, 256>>>(x, basis_A);                        // 3
    k_u_fill<<<BATCH / 256, 256>>>();                                // 4
    k_gemm<<<CT_TILES * BT_TILES, GTHREADS, DYN_SMEM>>>(out, base_b); // 5
}

// round 13
// speedup vs baseline: 1.0878x; 1.0878x over previous
#include <cuda_runtime.h>
#include <cuda_fp16.h>
#include <cstdint>
#include <cstddef>

// ---------------- problem constants ----------------
#define NCLS      50257
#define NCLS_PAD  50432            // 394 * 128
#define DM        2048
#define BATCH     2048
#define HID       128
#define NB        8
#define RK        4
#define KEXT      32               // NB*RK
#define KTOT      2112             // 2048 + 64-pad -> 33*64
#define KCH       64               // halves per K chunk (128 bytes)
#define NCHUNK    33
#define LN_EPS    1e-5f

#define M_TILE    128              // classes per CTA
#define N_TILE    128              // batch per CTA
#define CT_TILES  394
#define BT_TILES  16

// smem: 3 stages x (A 16KB | B 16KB) = 96KB; epilogue reuses as fp32 tile
#define STAGE_BYTES 32768
#define SM_B_OFF    16384
#define EPLD        132                      // 128*132*4 = 67.6KB < 96KB
#define DYN_SMEM    (3 * STAGE_BYTES)        // 98304 -> 2 CTAs/SM

// ---------------- device scratch ----------------
__device__ __align__(1024) __half g_W2[(size_t)NCLS_PAD * KTOT];  // ~213 MB
__device__ __align__(1024) __half g_A2[(size_t)BATCH * KTOT];     // ~8.7 MB
__device__ float g_coeffs[BATCH * NB];
__device__ float g_y[BATCH * NB * RK];

// ---------------- PTX helpers (base PTX only) ----------------
__device__ __forceinline__ uint32_t smem_u32(const void* p) {
    return (uint32_t)__cvta_generic_to_shared(p);
}
__device__ __forceinline__ void cp16(uint32_t dst, const void* src) {
    asm volatile("cp.async.cg.shared.global [%0], [%1], 16;" :: "r"(dst), "l"(src) : "memory");
}
__device__ __forceinline__ void ldsm4(uint32_t* r, uint32_t a) {
    asm volatile("ldmatrix.sync.aligned.m8n8.x4.shared.b16 {%0,%1,%2,%3}, [%4];"
                 : "=r"(r[0]), "=r"(r[1]), "=r"(r[2]), "=r"(r[3]) : "r"(a));
}
__device__ __forceinline__ void mma16816(float* c, const uint32_t* a,
                                         uint32_t b0, uint32_t b1) {
    asm volatile(
        "mma.sync.aligned.m16n8k16.row.col.f32.f16.f16.f32 "
        "{%0,%1,%2,%3}, {%4,%5,%6,%7}, {%8,%9}, {%0,%1,%2,%3};"
        : "+f"(c[0]), "+f"(c[1]), "+f"(c[2]), "+f"(c[3])
        : "r"(a[0]), "r"(a[1]), "r"(a[2]), "r"(a[3]), "r"(b0), "r"(b1));
}

// ============================================================================
// prep kernels (unchanged)
// ============================================================================

__global__ void k_conv_x(const float* __restrict__ x) {
    int gid = blockIdx.x * blockDim.x + threadIdx.x;
    const float4* xv = (const float4*)x;
    float4 a = xv[gid * 2];
    float4 b = xv[gid * 2 + 1];
    __half2 p[4];
    p[0] = __floats2half2_rn(a.x, a.y);
    p[1] = __floats2half2_rn(a.z, a.w);
    p[2] = __floats2half2_rn(b.x, b.y);
    p[3] = __floats2half2_rn(b.z, b.w);
    int brow = gid >> 8;
    int col8 = gid & 255;
    *(uint4*)(g_A2 + (size_t)brow * KTOT + col8 * 8) = *(uint4*)p;
}

__global__ void k_prep_w2(const float* __restrict__ base_w,
                          const float* __restrict__ basis_B) {
    int c = blockIdx.x;
    int t = threadIdx.x;
    __half* dst = g_W2 + (size_t)c * KTOT;
    if (c >= NCLS) {
        uint4 z = {0, 0, 0, 0};
        *(uint4*)(dst + t * 8) = z;
        if (t < 8) *(uint4*)(dst + DM + t * 8) = z;
        return;
    }
    {
        const float4* p = (const float4*)(base_w + (size_t)c * DM + t * 8);
        float4 a = p[0], b = p[1];
        __half h[8];
        h[0] = __float2half_rn(a.x); h[1] = __float2half_rn(a.y);
        h[2] = __float2half_rn(a.z); h[3] = __float2half_rn(a.w);
        h[4] = __float2half_rn(b.x); h[5] = __float2half_rn(b.y);
        h[6] = __float2half_rn(b.z); h[7] = __float2half_rn(b.w);
        *(uint4*)(dst + t * 8) = *(uint4*)h;
    }
    if (t < 8) {
        __half h[8];
        #pragma unroll
        for (int j = 0; j < 8; j++) {
            int idx = t * 8 + j;
            if (idx < KEXT) {
                int n = idx >> 2, r = idx & 3;
                h[j] = __float2half_rn(basis_B[((size_t)n * NCLS + c) * RK + r]);
            } else {
                h[j] = __ushort_as_half(0);
            }
        }
        *(uint4*)(dst + DM + t * 8) = *(uint4*)h;
    }
}

__global__ void __launch_bounds__(256)
k_ctx(const float* __restrict__ context,
      const float* __restrict__ ctx_w,
      const float* __restrict__ ctx_b,
      const float* __restrict__ ln_g,
      const float* __restrict__ ln_b,
      const float* __restrict__ coeff_w,
      const float* __restrict__ coeff_b) {
    __shared__ float sX[8][DM];
    __shared__ float sH[8][HID + 4];
    int tid = threadIdx.x;
    int b0 = blockIdx.x * 8;

    #pragma unroll
    for (int i = 0; i < 16; i++) {
        int e = tid + i * 256;
        int r = e >> 9, d4 = e & 511;
        *(float4*)&sX[r][d4 * 4] =
            *(const float4*)(context + (size_t)(b0 + r) * DM + d4 * 4);
    }
    __syncthreads();

    const int jq = tid >> 3;
    const int dg = tid & 7;
    float acc[8][4];
    #pragma unroll
    for (int r = 0; r < 8; r++)
        #pragma unroll
        for (int jj = 0; jj < 4; jj++) acc[r][jj] = 0.f;

    #pragma unroll 4
    for (int kk = 0; kk < DM; kk += 32) {
        float4 w4[4];
        #pragma unroll
        for (int jj = 0; jj < 4; jj++)
            w4[jj] = *(const float4*)(ctx_w + (size_t)(jq * 4 + jj) * DM + kk + dg * 4);
        #pragma unroll
        for (int r = 0; r < 8; r++) {
            float4 x4 = *(float4*)&sX[r][kk + dg * 4];
            #pragma unroll
            for (int jj = 0; jj < 4; jj++)
                acc[r][jj] += x4.x * w4[jj].x + x4.y * w4[jj].y +
                              x4.z * w4[jj].z + x4.w * w4[jj].w;
        }
    }
    #pragma unroll
    for (int off = 1; off < 8; off <<= 1)
        #pragma unroll
        for (int r = 0; r < 8; r++)
            #pragma unroll
            for (int jj = 0; jj < 4; jj++)
                acc[r][jj] += __shfl_xor_sync(0xffffffffu, acc[r][jj], off);
    if (dg == 0) {
        #pragma unroll
        for (int r = 0; r < 8; r++)
            #pragma unroll
            for (int jj = 0; jj < 4; jj++)
                sH[r][jq * 4 + jj] = acc[r][jj] + ctx_b[jq * 4 + jj];
    }
    __syncthreads();

    int wid = tid >> 5, lane = tid & 31;
    float v[4];
    #pragma unroll
    for (int j = 0; j < 4; j++) v[j] = sH[wid][lane * 4 + j];
    float s1 = v[0] + v[1] + v[2] + v[3];
    float s2 = v[0]*v[0] + v[1]*v[1] + v[2]*v[2] + v[3]*v[3];
    #pragma unroll
    for (int m = 16; m; m >>= 1) {
        s1 += __shfl_xor_sync(0xffffffffu, s1, m);
        s2 += __shfl_xor_sync(0xffffffffu, s2, m);
    }
    float mu = s1 * (1.0f / HID);
    float var = s2 * (1.0f / HID) - mu * mu;
    float inv = rsqrtf(var + LN_EPS);
    #pragma unroll
    for (int j = 0; j < 4; j++) {
        float hn = (v[j] - mu) * inv * ln_g[lane * 4 + j] + ln_b[lane * 4 + j];
        v[j] = 0.5f * hn * (1.0f + erff(hn * 0.70710678118654752f));
    }
    #pragma unroll
    for (int n = 0; n < NB; n++) {
        float d = 0.f;
        #pragma unroll
        for (int j = 0; j < 4; j++) d += v[j] * coeff_w[(size_t)n * HID + lane * 4 + j];
        #pragma unroll
        for (int m = 16; m; m >>= 1) d += __shfl_xor_sync(0xffffffffu, d, m);
        if (lane == 0) g_coeffs[(size_t)(b0 + wid) * NB + n] = d + coeff_b[n];
    }
}

__global__ void __launch_bounds__(256)
k_y_gemm(const float* __restrict__ x, const float* __restrict__ basis_A) {
    __shared__ float sX[4][DM];
    int tid = threadIdx.x;
    int b0 = blockIdx.x * 4;
    #pragma unroll
    for (int i = 0; i < 8; i++) {
        int e = tid + i * 256;
        int r = e >> 9, d4 = e & 511;
        *(float4*)&sX[r][d4 * 4] =
            *(const float4*)(x + (size_t)(b0 + r) * DM + d4 * 4);
    }
    __syncthreads();

    const int nr = tid >> 3;
    const int dg = tid & 7;
    float acc[4] = {};
    #pragma unroll 4
    for (int kk = 0; kk < DM; kk += 32) {
        float4 w4 = *(const float4*)(basis_A + (size_t)nr * DM + kk + dg * 4);
        #pragma unroll
        for (int r = 0; r < 4; r++) {
            float4 x4 = *(float4*)&sX[r][kk + dg * 4];
            acc[r] += x4.x * w4.x + x4.y * w4.y + x4.z * w4.z + x4.w * w4.w;
        }
    }
    #pragma unroll
    for (int off = 1; off < 8; off <<= 1)
        #pragma unroll
        for (int r = 0; r < 4; r++)
            acc[r] += __shfl_xor_sync(0xffffffffu, acc[r], off);
    if (dg == 0) {
        #pragma unroll
        for (int r = 0; r < 4; r++)
            g_y[(size_t)(b0 + r) * 32 + nr] = acc[r];
    }
}

__global__ void k_u_fill() {
    int row = blockIdx.x * blockDim.x + threadIdx.x;
    if (row >= BATCH) return;
    float c[NB], z[RK] = {};
    #pragma unroll
    for (int n = 0; n < NB; n++) c[n] = g_coeffs[(size_t)row * NB + n];
    #pragma unroll
    for (int n = 0; n < NB; n++)
        #pragma unroll
        for (int r = 0; r < RK; r++) z[r] += c[n] * g_y[(size_t)row * 32 + n * RK + r];
    __half u[KEXT];
    #pragma unroll
    for (int n = 0; n < NB; n++)
        #pragma unroll
        for (int r = 0; r < RK; r++) u[n * RK + r] = __float2half_rn(c[n] * z[r]);
    __half* dst = g_A2 + (size_t)row * KTOT + DM;
    #pragma unroll
    for (int j = 0; j < KEXT; j++) dst[j] = u[j];
    #pragma unroll
    for (int j = 0; j < 32; j++) dst[KEXT + j] = __ushort_as_half(0);
}

// ============================================================================
// main GEMM (HMMA): D[class][batch] = W2 @ A2^T + base_b
// CTA: 128 cls x 128 batch, 256 threads = 8 warps (2m x 4n, warp 64x32),
// 3-stage x 32KB -> 2 CTAs per SM; inter-CTA overlap hides barrier/drain
// ============================================================================

__device__ __forceinline__ void load_chunk(int ct, int bt, int chunk,
                                           uint32_t sb, int tid) {
    #pragma unroll
    for (int i = 0; i < 8; i++) {
        int e = tid + i * 256;                 // 0..2047
        const __half* src;
        uint32_t dst;
        if (e < 1024) {                        // A: 128 class rows x 8 segs
            int r = e >> 3, seg = e & 7;
            src = g_W2 + (size_t)(ct * M_TILE + r) * KTOT + chunk * KCH + seg * 8;
            dst = sb + r * 128 + ((seg ^ (r & 7)) << 4);
        } else {                               // B: 128 batch rows x 8 segs
            int e2 = e - 1024;
            int r = e2 >> 3, seg = e2 & 7;
            src = g_A2 + (size_t)(bt * N_TILE + r) * KTOT + chunk * KCH + seg * 8;
            dst = sb + SM_B_OFF + r * 128 + ((seg ^ (r & 7)) << 4);
        }
        cp16(dst, src);
    }
}

__global__ void __launch_bounds__(256, 2)
k_gemm(float* __restrict__ out, const float* __restrict__ base_b) {
    extern __shared__ char smem[];
    const uint32_t smb = smem_u32(smem);
    const int tid = threadIdx.x;
    const int wid = tid >> 5, lane = tid & 31;
    const int bt = blockIdx.x & 15;
    const int ct = blockIdx.x >> 4;
    const int wm = (wid & 1) * 64;             // warp m (class) offset
    const int wn = (wid >> 1) * 32;            // warp n (batch) offset

    const int j = lane >> 3, rl = lane & 7;
    const int arow = wm + ((j & 1) << 3) + rl;
    const int brow = wn + ((j & 1) << 3) + rl;
    const int usel = j >> 1;

    float acc[4][4][4];                        // 64 regs
    #pragma unroll
    for (int a = 0; a < 4; a++)
        #pragma unroll
        for (int b = 0; b < 4; b++)
            #pragma unroll
            for (int cc = 0; cc < 4; cc++) acc[a][b][cc] = 0.f;

    // prologue: stages 0,1
    #pragma unroll
    for (int c = 0; c < 2; c++) {
        load_chunk(ct, bt, c, smb + c * STAGE_BYTES, tid);
        asm volatile("cp.async.commit_group;" ::: "memory");
    }

    int sidx = 0;                              // stage index of chunk c
    #pragma unroll 1
    for (int c = 0; c < NCHUNK; c++) {
        const uint32_t sb = smb + sidx * STAGE_BYTES;
        asm volatile("cp.async.wait_group 1;" ::: "memory");
        __syncthreads();

        int n = c + 2;
        int nsidx = sidx + 2; if (nsidx >= 3) nsidx -= 3;
        if (n < NCHUNK) load_chunk(ct, bt, n, smb + nsidx * STAGE_BYTES, tid);
        asm volatile("cp.async.commit_group;" ::: "memory");

        #pragma unroll
        for (int k16 = 0; k16 < 4; k16++) {
            uint32_t af[4][4], bf[2][4];
            #pragma unroll
            for (int mt = 0; mt < 4; mt++) {
                int row = arow + mt * 16;
                ldsm4(af[mt], sb + row * 128 + (((k16 * 2 + usel) ^ (row & 7)) << 4));
            }
            #pragma unroll
            for (int nt2 = 0; nt2 < 2; nt2++) {
                int row = brow + nt2 * 16;
                ldsm4(bf[nt2], sb + SM_B_OFF + row * 128 +
                               (((k16 * 2 + usel) ^ (row & 7)) << 4));
            }
            #pragma unroll
            for (int mt = 0; mt < 4; mt++)
                #pragma unroll
                for (int nt2 = 0; nt2 < 2; nt2++) {
                    mma16816(acc[mt][2 * nt2 + 0], af[mt], bf[nt2][0], bf[nt2][2]);
                    mma16816(acc[mt][2 * nt2 + 1], af[mt], bf[nt2][1], bf[nt2][3]);
                }
        }
        sidx++; if (sidx >= 3) sidx = 0;
    }

    // epilogue: stage through smem, store coalesced
    asm volatile("cp.async.wait_group 0;" ::: "memory");
    __syncthreads();

    float* ep = (float*)smem;                  // 128 rows x EPLD floats
    const int mr = lane >> 2;
    const int nc = (lane & 3) * 2;

    #pragma unroll
    for (int mt = 0; mt < 4; mt++)
        #pragma unroll
        for (int rep = 0; rep < 2; rep++) {
            int cl = wm + mt * 16 + rep * 8 + mr;
            #pragma unroll
            for (int nt = 0; nt < 4; nt++) {
                int bl = wn + nt * 8 + nc;
                ep[bl * EPLD + cl]       = acc[mt][nt][rep * 2 + 0];
                ep[(bl + 1) * EPLD + cl] = acc[mt][nt][rep * 2 + 1];
            }
        }
    __syncthreads();

    const int cls_base = ct * M_TILE;
    float bias[4];
    bool okc[4];
    #pragma unroll
    for (int jj = 0; jj < 4; jj++) {
        int cls = cls_base + jj * 32 + lane;
        okc[jj] = (cls < NCLS);
        bias[jj] = okc[jj] ? base_b[cls] : 0.f;
    }
    #pragma unroll 1
    for (int r = wid; r < N_TILE; r += 8) {
        size_t obase = (size_t)(bt * N_TILE + r) * NCLS + cls_base;
        const float* erow = ep + r * EPLD;
        #pragma unroll
        for (int jj = 0; jj < 4; jj++)
            if (okc[jj])
                out[obase + jj * 32 + lane] = erow[jj * 32 + lane] + bias[jj];
    }
}

// ============================================================================
// launch
// ============================================================================
extern "C" void kernel_launch(void* const* d_in, const int* in_sizes, int n_in,
                              void* d_out, int out_size) {
    const float* x        = (const float*)d_in[0];
    const float* context  = (const float*)d_in[1];
    const float* base_w   = (const float*)d_in[2];
    const float* base_b   = (const float*)d_in[3];
    const float* ctx_w    = (const float*)d_in[4];
    const float* ctx_b    = (const float*)d_in[5];
    const float* ln_g     = (const float*)d_in[6];
    const float* ln_b     = (const float*)d_in[7];
    const float* coeff_w  = (const float*)d_in[8];
    const float* coeff_b  = (const float*)d_in[9];
    const float* basis_A  = (const float*)d_in[10];
    const float* basis_B  = (const float*)d_in[11];
    float* out = (float*)d_out;

    cudaFuncSetAttribute(k_gemm, cudaFuncAttributeMaxDynamicSharedMemorySize, DYN_SMEM);

    k_prep_w2<<<NCLS_PAD, 256>>>(base_w, basis_B);                   // 0
    k_conv_x<<<BATCH * DM / 8 / 256, 256>>>(x);                      // 1
    k_ctx<<<BATCH / 8, 256>>>(context, ctx_w, ctx_b, ln_g, ln_b, coeff_w, coeff_b); // 2
    k_y_gemm<<<BATCH / 4, 256>>>(x, basis_A);                        // 3
    k_u_fill<<<BATCH / 256, 256>>>();                                // 4
    k_gemm<<<CT_TILES * BT_TILES, 256, DYN_SMEM>>>(out, base_b);     // 5
}

// round 14
// speedup vs baseline: 1.1225x; 1.0319x over previous
#include <cuda_runtime.h>
#include <cuda_fp16.h>
#include <cstdint>
#include <cstddef>

// ---------------- problem constants ----------------
#define NCLS      50257
#define NCLS_PAD  50304            // 393 * 128
#define DM        2048
#define BATCH     2048
#define HID       128
#define NB        8
#define RK        4
#define KEXT      32               // NB*RK
#define KTOT      2112             // 2048 + 64-pad -> 33*64
#define KCH       64               // halves per K chunk (128 bytes)
#define NCHUNK    33
#define LN_EPS    1e-5f

#define M_TILE    128              // classes per CTA
#define N_TILE    128              // batch per CTA
#define CT_TILES  393
#define BT_TILES  16

// smem: 3 stages x (A 16KB | B 16KB) = 96KB; epilogue reuses as fp32 tile
#define STAGE_BYTES 32768
#define SM_B_OFF    16384
#define EPLD        132                      // 128*132*4 = 67.6KB < 96KB
#define DYN_SMEM    (3 * STAGE_BYTES)        // 98304 -> 2 CTAs/SM

// prep kernel B block ranges
#define W2_BLKS    NCLS_PAD
#define CONV_BLKS  (BATCH * DM / 8 / 256)    // 2048
#define UFILL_BLKS (BATCH / 256)             // 8

// ---------------- device scratch ----------------
__device__ __align__(1024) __half g_W2[(size_t)NCLS_PAD * KTOT];  // ~212 MB
__device__ __align__(1024) __half g_A2[(size_t)BATCH * KTOT];     // ~8.7 MB
__device__ float g_coeffs[BATCH * NB];
__device__ float g_y[BATCH * NB * RK];

// ---------------- PTX helpers (base PTX only) ----------------
__device__ __forceinline__ uint32_t smem_u32(const void* p) {
    return (uint32_t)__cvta_generic_to_shared(p);
}
__device__ __forceinline__ void cp16(uint32_t dst, const void* src) {
    asm volatile("cp.async.cg.shared.global [%0], [%1], 16;" :: "r"(dst), "l"(src) : "memory");
}
__device__ __forceinline__ void ldsm4(uint32_t* r, uint32_t a) {
    asm volatile("ldmatrix.sync.aligned.m8n8.x4.shared.b16 {%0,%1,%2,%3}, [%4];"
                 : "=r"(r[0]), "=r"(r[1]), "=r"(r[2]), "=r"(r[3]) : "r"(a));
}
__device__ __forceinline__ void mma16816(float* c, const uint32_t* a,
                                         uint32_t b0, uint32_t b1) {
    asm volatile(
        "mma.sync.aligned.m16n8k16.row.col.f32.f16.f16.f32 "
        "{%0,%1,%2,%3}, {%4,%5,%6,%7}, {%8,%9}, {%0,%1,%2,%3};"
        : "+f"(c[0]), "+f"(c[1]), "+f"(c[2]), "+f"(c[3])
        : "r"(a[0]), "r"(a[1]), "r"(a[2]), "r"(a[3]), "r"(b0), "r"(b1));
}

// ============================================================================
// prep kernel A: [blocks 0..255] ctx MLP+LN+GELU+coeffs, [256..511] y-GEMM
// ============================================================================
__global__ void __launch_bounds__(256)
k_prepA(const float* __restrict__ x,
        const float* __restrict__ context,
        const float* __restrict__ ctx_w,
        const float* __restrict__ ctx_b,
        const float* __restrict__ ln_g,
        const float* __restrict__ ln_b,
        const float* __restrict__ coeff_w,
        const float* __restrict__ coeff_b,
        const float* __restrict__ basis_A) {
    __shared__ float sX[8][DM];          // 64 KB
    __shared__ float sH[8][HID + 4];
    int tid = threadIdx.x;

    if (blockIdx.x < 256) {
        // ---------------- ctx branch: 8 batch rows ----------------
        int b0 = blockIdx.x * 8;
        #pragma unroll
        for (int i = 0; i < 16; i++) {
            int e = tid + i * 256;
            int r = e >> 9, d4 = e & 511;
            *(float4*)&sX[r][d4 * 4] =
                *(const float4*)(context + (size_t)(b0 + r) * DM + d4 * 4);
        }
        __syncthreads();

        const int jq = tid >> 3;
        const int dg = tid & 7;
        float acc[8][4];
        #pragma unroll
        for (int r = 0; r < 8; r++)
            #pragma unroll
            for (int jj = 0; jj < 4; jj++) acc[r][jj] = 0.f;

        #pragma unroll 4
        for (int kk = 0; kk < DM; kk += 32) {
            float4 w4[4];
            #pragma unroll
            for (int jj = 0; jj < 4; jj++)
                w4[jj] = *(const float4*)(ctx_w + (size_t)(jq * 4 + jj) * DM + kk + dg * 4);
            #pragma unroll
            for (int r = 0; r < 8; r++) {
                float4 x4 = *(float4*)&sX[r][kk + dg * 4];
                #pragma unroll
                for (int jj = 0; jj < 4; jj++)
                    acc[r][jj] += x4.x * w4[jj].x + x4.y * w4[jj].y +
                                  x4.z * w4[jj].z + x4.w * w4[jj].w;
            }
        }
        #pragma unroll
        for (int off = 1; off < 8; off <<= 1)
            #pragma unroll
            for (int r = 0; r < 8; r++)
                #pragma unroll
                for (int jj = 0; jj < 4; jj++)
                    acc[r][jj] += __shfl_xor_sync(0xffffffffu, acc[r][jj], off);
        if (dg == 0) {
            #pragma unroll
            for (int r = 0; r < 8; r++)
                #pragma unroll
                for (int jj = 0; jj < 4; jj++)
                    sH[r][jq * 4 + jj] = acc[r][jj] + ctx_b[jq * 4 + jj];
        }
        __syncthreads();

        int wid = tid >> 5, lane = tid & 31;
        float v[4];
        #pragma unroll
        for (int j = 0; j < 4; j++) v[j] = sH[wid][lane * 4 + j];
        float s1 = v[0] + v[1] + v[2] + v[3];
        float s2 = v[0]*v[0] + v[1]*v[1] + v[2]*v[2] + v[3]*v[3];
        #pragma unroll
        for (int m = 16; m; m >>= 1) {
            s1 += __shfl_xor_sync(0xffffffffu, s1, m);
            s2 += __shfl_xor_sync(0xffffffffu, s2, m);
        }
        float mu = s1 * (1.0f / HID);
        float var = s2 * (1.0f / HID) - mu * mu;
        float inv = rsqrtf(var + LN_EPS);
        #pragma unroll
        for (int j = 0; j < 4; j++) {
            float hn = (v[j] - mu) * inv * ln_g[lane * 4 + j] + ln_b[lane * 4 + j];
            v[j] = 0.5f * hn * (1.0f + erff(hn * 0.70710678118654752f));
        }
        #pragma unroll
        for (int n = 0; n < NB; n++) {
            float d = 0.f;
            #pragma unroll
            for (int j = 0; j < 4; j++) d += v[j] * coeff_w[(size_t)n * HID + lane * 4 + j];
            #pragma unroll
            for (int m = 16; m; m >>= 1) d += __shfl_xor_sync(0xffffffffu, d, m);
            if (lane == 0) g_coeffs[(size_t)(b0 + wid) * NB + n] = d + coeff_b[n];
        }
    } else {
        // ---------------- y branch: 8 batch rows ----------------
        int b0 = (blockIdx.x - 256) * 8;
        #pragma unroll
        for (int i = 0; i < 16; i++) {
            int e = tid + i * 256;
            int r = e >> 9, d4 = e & 511;
            *(float4*)&sX[r][d4 * 4] =
                *(const float4*)(x + (size_t)(b0 + r) * DM + d4 * 4);
        }
        __syncthreads();

        const int nr = tid >> 3;
        const int dg = tid & 7;
        float acc[8];
        #pragma unroll
        for (int r = 0; r < 8; r++) acc[r] = 0.f;
        #pragma unroll 4
        for (int kk = 0; kk < DM; kk += 32) {
            float4 w4 = *(const float4*)(basis_A + (size_t)nr * DM + kk + dg * 4);
            #pragma unroll
            for (int r = 0; r < 8; r++) {
                float4 x4 = *(float4*)&sX[r][kk + dg * 4];
                acc[r] += x4.x * w4.x + x4.y * w4.y + x4.z * w4.z + x4.w * w4.w;
            }
        }
        #pragma unroll
        for (int off = 1; off < 8; off <<= 1)
            #pragma unroll
            for (int r = 0; r < 8; r++)
                acc[r] += __shfl_xor_sync(0xffffffffu, acc[r], off);
        if (dg == 0) {
            #pragma unroll
            for (int r = 0; r < 8; r++)
                g_y[(size_t)(b0 + r) * 32 + nr] = acc[r];
        }
    }
}

// ============================================================================
// prep kernel B: [0..W2_BLKS) w2-convert | [+CONV_BLKS) x-convert | [+8) u-fill
// ============================================================================
__global__ void __launch_bounds__(256)
k_prepB(const float* __restrict__ base_w,
        const float* __restrict__ basis_B,
        const float* __restrict__ x) {
    int bid = blockIdx.x;
    int t = threadIdx.x;

    if (bid < W2_BLKS) {
        int c = bid;
        __half* dst = g_W2 + (size_t)c * KTOT;
        if (c >= NCLS) {
            uint4 z = {0, 0, 0, 0};
            *(uint4*)(dst + t * 8) = z;
            if (t < 8) *(uint4*)(dst + DM + t * 8) = z;
            return;
        }
        {
            const float4* p = (const float4*)(base_w + (size_t)c * DM + t * 8);
            float4 a = p[0], b = p[1];
            __half h[8];
            h[0] = __float2half_rn(a.x); h[1] = __float2half_rn(a.y);
            h[2] = __float2half_rn(a.z); h[3] = __float2half_rn(a.w);
            h[4] = __float2half_rn(b.x); h[5] = __float2half_rn(b.y);
            h[6] = __float2half_rn(b.z); h[7] = __float2half_rn(b.w);
            *(uint4*)(dst + t * 8) = *(uint4*)h;
        }
        if (t < 8) {
            __half h[8];
            #pragma unroll
            for (int j = 0; j < 8; j++) {
                int idx = t * 8 + j;
                if (idx < KEXT) {
                    int n = idx >> 2, r = idx & 3;
                    h[j] = __float2half_rn(basis_B[((size_t)n * NCLS + c) * RK + r]);
                } else {
                    h[j] = __ushort_as_half(0);
                }
            }
            *(uint4*)(dst + DM + t * 8) = *(uint4*)h;
        }
    } else if (bid < W2_BLKS + CONV_BLKS) {
        // x fp32 -> A2[:, 0:2048] half
        int gid = (bid - W2_BLKS) * 256 + t;
        const float4* xv = (const float4*)x;
        float4 a = xv[gid * 2];
        float4 b = xv[gid * 2 + 1];
        __half2 p[4];
        p[0] = __floats2half2_rn(a.x, a.y);
        p[1] = __floats2half2_rn(a.z, a.w);
        p[2] = __floats2half2_rn(b.x, b.y);
        p[3] = __floats2half2_rn(b.z, b.w);
        int brow = gid >> 8;
        int col8 = gid & 255;
        *(uint4*)(g_A2 + (size_t)brow * KTOT + col8 * 8) = *(uint4*)p;
    } else {
        // u-fill: A2[:, 2048:2112]
        int row = (bid - W2_BLKS - CONV_BLKS) * 256 + t;
        float c[NB], z[RK] = {};
        #pragma unroll
        for (int n = 0; n < NB; n++) c[n] = g_coeffs[(size_t)row * NB + n];
        #pragma unroll
        for (int n = 0; n < NB; n++)
            #pragma unroll
            for (int r = 0; r < RK; r++) z[r] += c[n] * g_y[(size_t)row * 32 + n * RK + r];
        __half u[KEXT];
        #pragma unroll
        for (int n = 0; n < NB; n++)
            #pragma unroll
            for (int r = 0; r < RK; r++) u[n * RK + r] = __float2half_rn(c[n] * z[r]);
        __half* dst = g_A2 + (size_t)row * KTOT + DM;
        #pragma unroll
        for (int j = 0; j < KEXT; j++) dst[j] = u[j];
        #pragma unroll
        for (int j = 0; j < 32; j++) dst[KEXT + j] = __ushort_as_half(0);
    }
}

// ============================================================================
// main GEMM (HMMA): D[class][batch] = W2 @ A2^T + base_b
// CTA: 128 cls x 128 batch, 8 warps (2m x 4n, warp 64x32), 2 CTAs/SM
// ============================================================================

__device__ __forceinline__ void load_chunk(int ct, int bt, int chunk,
                                           uint32_t sb, int tid) {
    #pragma unroll
    for (int i = 0; i < 8; i++) {
        int e = tid + i * 256;                 // 0..2047
        const __half* src;
        uint32_t dst;
        if (e < 1024) {                        // A: 128 class rows x 8 segs
            int r = e >> 3, seg = e & 7;
            src = g_W2 + (size_t)(ct * M_TILE + r) * KTOT + chunk * KCH + seg * 8;
            dst = sb + r * 128 + ((seg ^ (r & 7)) << 4);
        } else {                               // B: 128 batch rows x 8 segs
            int e2 = e - 1024;
            int r = e2 >> 3, seg = e2 & 7;
            src = g_A2 + (size_t)(bt * N_TILE + r) * KTOT + chunk * KCH + seg * 8;
            dst = sb + SM_B_OFF + r * 128 + ((seg ^ (r & 7)) << 4);
        }
        cp16(dst, src);
    }
}

__global__ void __launch_bounds__(256, 2)
k_gemm(float* __restrict__ out, const float* __restrict__ base_b) {
    extern __shared__ char smem[];
    const uint32_t smb = smem_u32(smem);
    const int tid = threadIdx.x;
    const int wid = tid >> 5, lane = tid & 31;
    const int bt = blockIdx.x & 15;
    const int ct = blockIdx.x >> 4;
    const int wm = (wid & 1) * 64;
    const int wn = (wid >> 1) * 32;

    const int j = lane >> 3, rl = lane & 7;
    const int arow = wm + ((j & 1) << 3) + rl;
    const int brow = wn + ((j & 1) << 3) + rl;
    const int usel = j >> 1;

    // hoist bias loads: latency hides under the mainloop
    const int cls_base = ct * M_TILE;
    float bias[4];
    bool okc[4];
    #pragma unroll
    for (int jj = 0; jj < 4; jj++) {
        int cls = cls_base + jj * 32 + lane;
        okc[jj] = (cls < NCLS);
        bias[jj] = okc[jj] ? base_b[cls] : 0.f;
    }

    float acc[4][4][4];
    #pragma unroll
    for (int a = 0; a < 4; a++)
        #pragma unroll
        for (int b = 0; b < 4; b++)
            #pragma unroll
            for (int cc = 0; cc < 4; cc++) acc[a][b][cc] = 0.f;

    #pragma unroll
    for (int c = 0; c < 2; c++) {
        load_chunk(ct, bt, c, smb + c * STAGE_BYTES, tid);
        asm volatile("cp.async.commit_group;" ::: "memory");
    }

    int sidx = 0;
    #pragma unroll 1
    for (int c = 0; c < NCHUNK; c++) {
        const uint32_t sb = smb + sidx * STAGE_BYTES;
        asm volatile("cp.async.wait_group 1;" ::: "memory");
        __syncthreads();

        int n = c + 2;
        int nsidx = sidx + 2; if (nsidx >= 3) nsidx -= 3;
        if (n < NCHUNK) load_chunk(ct, bt, n, smb + nsidx * STAGE_BYTES, tid);
        asm volatile("cp.async.commit_group;" ::: "memory");

        #pragma unroll
        for (int k16 = 0; k16 < 4; k16++) {
            uint32_t af[4][4], bf[2][4];
            #pragma unroll
            for (int mt = 0; mt < 4; mt++) {
                int row = arow + mt * 16;
                ldsm4(af[mt], sb + row * 128 + (((k16 * 2 + usel) ^ (row & 7)) << 4));
            }
            #pragma unroll
            for (int nt2 = 0; nt2 < 2; nt2++) {
                int row = brow + nt2 * 16;
                ldsm4(bf[nt2], sb + SM_B_OFF + row * 128 +
                               (((k16 * 2 + usel) ^ (row & 7)) << 4));
            }
            #pragma unroll
            for (int mt = 0; mt < 4; mt++)
                #pragma unroll
                for (int nt2 = 0; nt2 < 2; nt2++) {
                    mma16816(acc[mt][2 * nt2 + 0], af[mt], bf[nt2][0], bf[nt2][2]);
                    mma16816(acc[mt][2 * nt2 + 1], af[mt], bf[nt2][1], bf[nt2][3]);
                }
        }
        sidx++; if (sidx >= 3) sidx = 0;
    }

    // epilogue: stage through smem, store coalesced
    asm volatile("cp.async.wait_group 0;" ::: "memory");
    __syncthreads();

    float* ep = (float*)smem;
    const int mr = lane >> 2;
    const int nc = (lane & 3) * 2;

    #pragma unroll
    for (int mt = 0; mt < 4; mt++)
        #pragma unroll
        for (int rep = 0; rep < 2; rep++) {
            int cl = wm + mt * 16 + rep * 8 + mr;
            #pragma unroll
            for (int nt = 0; nt < 4; nt++) {
                int bl = wn + nt * 8 + nc;
                ep[bl * EPLD + cl]       = acc[mt][nt][rep * 2 + 0];
                ep[(bl + 1) * EPLD + cl] = acc[mt][nt][rep * 2 + 1];
            }
        }
    __syncthreads();

    #pragma unroll 1
    for (int r = wid; r < N_TILE; r += 8) {
        size_t obase = (size_t)(bt * N_TILE + r) * NCLS + cls_base;
        const float* erow = ep + r * EPLD;
        #pragma unroll
        for (int jj = 0; jj < 4; jj++)
            if (okc[jj])
                out[obase + jj * 32 + lane] = erow[jj * 32 + lane] + bias[jj];
    }
}

// ============================================================================
// launch: 3 kernels total (ncu -s 5 lands on k_gemm in replay 2)
// ============================================================================
extern "C" void kernel_launch(void* const* d_in, const int* in_sizes, int n_in,
                              void* d_out, int out_size) {
    const float* x        = (const float*)d_in[0];
    const float* context  = (const float*)d_in[1];
    const float* base_w   = (const float*)d_in[2];
    const float* base_b   = (const float*)d_in[3];
    const float* ctx_w    = (const float*)d_in[4];
    const float* ctx_b    = (const float*)d_in[5];
    const float* ln_g     = (const float*)d_in[6];
    const float* ln_b     = (const float*)d_in[7];
    const float* coeff_w  = (const float*)d_in[8];
    const float* coeff_b  = (const float*)d_in[9];
    const float* basis_A  = (const float*)d_in[10];
    const float* basis_B  = (const float*)d_in[11];
    float* out = (float*)d_out;

    cudaFuncSetAttribute(k_gemm, cudaFuncAttributeMaxDynamicSharedMemorySize, DYN_SMEM);

    k_prepA<<<512, 256>>>(x, context, ctx_w, ctx_b, ln_g, ln_b,
                          coeff_w, coeff_b, basis_A);                 // 0
    k_prepB<<<W2_BLKS + CONV_BLKS + UFILL_BLKS, 256>>>(base_w, basis_B, x); // 1
    k_gemm<<<CT_TILES * BT_TILES, 256, DYN_SMEM>>>(out, base_b);      // 2
}